// round 12
// baseline (speedup 1.0000x reference)
#include <cuda_runtime.h>
#include <cstdint>

#define BB 512
#define TT 4096
#define SS 64
#define MM 125
#define CHUNK 512                 // time-steps per producer/consumer chunk
#define NCHUNK (TT / CHUNK)       // 8

// packed f32x2 FMA — only reachable via PTX (ptxas never auto-fuses)
__device__ __forceinline__ void ffma2(float2& d, float2 a, float2 b, float2 c) {
    asm("fma.rn.f32x2 %0, %1, %2, %3;"
        : "=l"(*(unsigned long long*)&d)
        : "l"(*(unsigned long long*)&a),
          "l"(*(unsigned long long*)&b),
          "l"(*(unsigned long long*)&c));
}

// per-step rendezvous of the 2 scan warps of one chain (64 threads)
__device__ __forceinline__ void scan_bar(int chain) {
    asm volatile("bar.sync %0, 64;" :: "r"(chain + 1) : "memory");
}
// per-chunk rendezvous: 2 scan warps + 1 decoder warp (96 threads)
__device__ __forceinline__ void chunk_bar(int chain) {
    asm volatile("bar.sync %0, 96;" :: "r"(chain + 5) : "memory");
}

// ---------------------------------------------------------------------------
// Fused kernel, 384 threads/CTA (12 warps, 4 chains):
//   warps 0-7 : scan warps; chain = w>>1, half = w&1 (pair spans 2 SMSPs)
//               lane owns ONE state s = half*32 + lane
//   warps 8-11: decoder warps, stream + argmax-decode chain w-8
// ---------------------------------------------------------------------------
__global__ void __launch_bounds__(384, 1) fused_hmm_kernel(
    const float* __restrict__ x,
    const float* __restrict__ Ivec,
    const float* __restrict__ A,
    const float* __restrict__ Bm,
    float* __restrict__ out)
{
    __shared__ float sB[MM * SS];                            // 32000 B, plain [m][s]
    __shared__ float sAlpha[4][2][SS];                       //  2048 B
    __shared__ __align__(16) unsigned char sObs[4][2][CHUNK];//  4096 B
    __shared__ float sHalf[4];

    const int tid  = threadIdx.x;
    const int w    = tid >> 5;
    const int lane = tid & 31;

    // stage Bm (layout already [125][64])
    for (int i = tid; i < (MM * SS) / 4; i += 384)
        ((float4*)sB)[i] = ((const float4*)Bm)[i];
    __syncthreads();

    if (w >= 8) {
        // ------------------ decoder warp for chain p ------------------
        const int p = w - 8;
        const int b = blockIdx.x * 4 + p;
        const float4* xc = (const float4*)(x + (size_t)b * TT * MM);
        for (int c = 0; c < NCHUNK; c++) {
            unsigned char* dst = sObs[p][c & 1];
            const float4* base = xc + c * (CHUNK * MM / 4);   // 16000 float4/chunk
            const unsigned jbase = c * (CHUNK * MM);
            const unsigned rbase = c * CHUNK;
            for (int i = lane; i < CHUNK * MM / 4; i += 32) {
                float4 v = __ldcs(base + i);
                unsigned j = jbase + 4u * i;
                if (v.x > 0.5f) { unsigned r = j / 125u;        dst[r - rbase] = (unsigned char)(j - r * 125u); }
                if (v.y > 0.5f) { unsigned r = (j + 1) / 125u;  dst[r - rbase] = (unsigned char)(j + 1 - r * 125u); }
                if (v.z > 0.5f) { unsigned r = (j + 2) / 125u;  dst[r - rbase] = (unsigned char)(j + 2 - r * 125u); }
                if (v.w > 0.5f) { unsigned r = (j + 3) / 125u;  dst[r - rbase] = (unsigned char)(j + 3 - r * 125u); }
            }
            chunk_bar(p);   // chunk c ready; scanners freed the other buffer by arriving
        }
    } else {
        // ------------------ scan warp: half of chain ------------------
        const int chain = w >> 1;
        const int half  = w & 1;
        const int s     = half * 32 + lane;   // the single state this lane owns
        const int b     = blockIdx.x * 4 + chain;

        // A column for state s, k-pair packed: aT[kp] = (A[2kp][s], A[2kp+1][s])
        float2 aT[32];
#pragma unroll
        for (int kp = 0; kp < 32; kp++)
            aT[kp] = make_float2(A[(2 * kp) * SS + s], A[(2 * kp + 1) * SS + s]);

        const float iv = Ivec[s];
        float u = 0.0f;
        int esum = 0;

        for (int c = 0; c < NCHUNK; c++) {
            chunk_bar(chain);
            const unsigned char* obs = sObs[chain][c & 1];
            for (int blk = 0; blk < CHUNK / 8; blk++) {
                uint2 ow = *(const uint2*)(obs + blk * 8);   // 8 obs bytes
#pragma unroll
                for (int i = 0; i < 8; i++) {
                    unsigned word = (i < 4) ? ow.x : ow.y;
                    int ob = (word >> ((i & 3) * 8)) & 0xff;
                    float e = sB[ob * SS + s];               // LDS.32, conflict-free

                    if (c == 0 && blk == 0 && i == 0) {
                        u = e * iv;                          // t=0: u = E0 * I
                    } else {
                        // read alpha of step t-1: buffer parity (i+1)&1
                        const float4* ap = (const float4*)sAlpha[chain][(i + 1) & 1];
                        float a0x;
                        float2 A0 = {0.f,0.f}, A1 = {0.f,0.f}, A2 = {0.f,0.f}, A3 = {0.f,0.f};
#pragma unroll
                        for (int q = 0; q < 16; q++) {
                            float4 f = ap[q];                // alpha[4q..4q+3] broadcast
                            if (q == 0) a0x = f.x;           // alpha[0] for renorm
                            float2 lo = make_float2(f.x, f.y);
                            float2 hi = make_float2(f.z, f.w);
                            if ((q & 3) == 0) { ffma2(A0, lo, aT[2*q], A0); ffma2(A0, hi, aT[2*q+1], A0); }
                            if ((q & 3) == 1) { ffma2(A1, lo, aT[2*q], A1); ffma2(A1, hi, aT[2*q+1], A1); }
                            if ((q & 3) == 2) { ffma2(A2, lo, aT[2*q], A2); ffma2(A2, hi, aT[2*q+1], A2); }
                            if ((q & 3) == 3) { ffma2(A3, lo, aT[2*q], A3); ffma2(A3, hi, aT[2*q+1], A3); }
                        }
                        float r = ((A0.x + A0.y) + (A1.x + A1.y))
                                + ((A2.x + A2.y) + (A3.x + A3.y));
                        u = e * r;

                        // block start (t ≡ 0 mod 8, t ≥ 8): exact power-of-two
                        // rescale derived from broadcast alpha[0] of step t-1 —
                        // both warps compute the identical ex with no traffic.
                        if (i == 0) {
                            int ex = (int)((__float_as_uint(a0x) >> 23) & 0xff) - 127;
                            esum += ex;
                            u *= __uint_as_float((unsigned)(127 - ex) << 23);   // 2^-ex
                        }
                    }

                    sAlpha[chain][i & 1][s] = u;             // STS.32
                    scan_bar(chain);                         // both halves visible
                }
            }
        }

        // final: warp-half sums, combine across the pair, one exact log
        float S = u;
#pragma unroll
        for (int o = 16; o; o >>= 1) S += __shfl_xor_sync(0xffffffffu, S, o);
        if (half == 1 && lane == 0) sHalf[chain] = S;
        scan_bar(chain);
        if (half == 0 && lane == 0)
            out[b] = (float)esum * 0.6931471805599453f + logf(S + sHalf[chain]);
    }
}

extern "C" void kernel_launch(void* const* d_in, const int* in_sizes, int n_in,
                              void* d_out, int out_size) {
    const float* x  = (const float*)d_in[0];   // [512, 4096, 125]
    const float* I  = (const float*)d_in[1];   // [1, 64]
    const float* A  = (const float*)d_in[2];   // [64, 64]
    const float* Bm = (const float*)d_in[3];   // [125, 64]
    float* out = (float*)d_out;                // [512, 1]

    fused_hmm_kernel<<<BB / 4, 384>>>(x, I, A, Bm, out);
}